// round 1
// baseline (speedup 1.0000x reference)
#include <cuda_runtime.h>
#include <math.h>

#define NN 8192
#define EE 262144
#define KK1 4096
#define KK2 2048
#define KK3 1024
#define NG 64

typedef unsigned int u32;

// ------------------------- workspace layout (floats) -------------------------
constexpr size_t O_X1   = 0;                 constexpr size_t S_X1   = (size_t)NN*32;
constexpr size_t O_X2   = O_X1+S_X1;         constexpr size_t S_X2   = (size_t)KK1*32;
constexpr size_t O_X3   = O_X2+S_X2;         constexpr size_t S_X3   = (size_t)KK1*64;
constexpr size_t O_X4   = O_X3+S_X3;         constexpr size_t S_X4   = (size_t)KK2*64;
constexpr size_t O_X5   = O_X4+S_X4;         constexpr size_t S_X5   = (size_t)KK2*128;
constexpr size_t O_X6   = O_X5+S_X5;         constexpr size_t S_X6   = (size_t)KK3*128;
constexpr size_t O_X7   = O_X6+S_X6;         constexpr size_t S_X7   = (size_t)KK3*256;
constexpr size_t O_XC8  = O_X7+S_X7;         constexpr size_t S_XC8  = (size_t)KK2*384;
constexpr size_t O_X9   = O_XC8+S_XC8;       constexpr size_t S_X9   = (size_t)KK2*128;
constexpr size_t O_XC10 = O_X9+S_X9;         constexpr size_t S_XC10 = (size_t)KK1*192;
constexpr size_t O_X11  = O_XC10+S_XC10;     constexpr size_t S_X11  = (size_t)KK1*64;
constexpr size_t O_XC12 = O_X11+S_X11;       constexpr size_t S_XC12 = (size_t)NN*96;
constexpr size_t O_X13  = O_XC12+S_XC12;     constexpr size_t S_X13  = (size_t)NN*32;
constexpr size_t O_Z    = O_X13+S_X13;       constexpr size_t S_Z    = 262144;
constexpr size_t O_AGG  = O_Z+S_Z;           constexpr size_t S_AGG  = 262144;
constexpr size_t O_DEG0 = O_AGG+S_AGG;       constexpr size_t S_DEG0 = NN;
constexpr size_t O_DINV0= O_DEG0+S_DEG0;     constexpr size_t S_DINV0= NN;
constexpr size_t O_DINV2= O_DINV0+S_DINV0;   constexpr size_t S_DINV2= KK1;
constexpr size_t O_DINV4= O_DINV2+S_DINV2;   constexpr size_t S_DINV4= KK2;
constexpr size_t O_DINV6= O_DINV4+S_DINV4;   constexpr size_t S_DINV6= KK3;
constexpr size_t O_S    = O_DINV6+S_DINV6;   constexpr size_t S_S    = NN;
constexpr size_t O_RANK = O_S+S_S;           constexpr size_t S_RANK = NN;
constexpr size_t O_POS0 = O_RANK+S_RANK;     constexpr size_t S_POS0 = NN;
constexpr size_t O_I2   = O_POS0+S_POS0;     constexpr size_t S_I2   = KK1;
constexpr size_t O_I4   = O_I2+S_I2;         constexpr size_t S_I4   = KK2;
constexpr size_t O_I6   = O_I4+S_I4;         constexpr size_t S_I6   = KK3;
constexpr size_t O_BM2  = O_I6+S_I6;         constexpr size_t S_BM2  = (size_t)KK1*(KK1/32);
constexpr size_t O_BM4  = O_BM2+S_BM2;       constexpr size_t S_BM4  = (size_t)KK2*(KK2/32);
constexpr size_t O_BM6  = O_BM4+S_BM4;       constexpr size_t S_BM6  = (size_t)KK3*(KK3/32);
constexpr size_t O_GSUM = O_BM6+S_BM6;       constexpr size_t S_GSUM = (size_t)NG*32;
constexpr size_t O_GMAX = O_GSUM+S_GSUM;     constexpr size_t S_GMAX = (size_t)NG*32;
constexpr size_t O_CNT  = O_GMAX+S_GMAX;     constexpr size_t S_CNT  = NG;
constexpr size_t O_INVN = O_CNT+S_CNT;       constexpr size_t S_INVN = 64;
constexpr size_t WS_TOTAL = O_INVN + S_INVN;

__device__ __align__(256) float g_ws[WS_TOTAL];

// ------------------------------- helpers -------------------------------------
__device__ __forceinline__ float eluf(float x) {
    return x > 0.f ? x : expm1f(x);
}
__device__ __forceinline__ unsigned ford(float f) {
    unsigned u = __float_as_uint(f);
    return (u & 0x80000000u) ? ~u : (u | 0x80000000u);
}
__device__ __forceinline__ float unford(unsigned u) {
    return __uint_as_float((u & 0x80000000u) ? (u & 0x7fffffffu) : ~u);
}

// ------------------------------- kernels -------------------------------------

// histogram of edge destinations
__global__ void k_deg0(const int* __restrict__ ei, int* __restrict__ deg) {
    int e = blockIdx.x * blockDim.x + threadIdx.x;
    if (e < EE) atomicAdd(&deg[ei[EE + e]], 1);
}

__global__ void k_dinv0(const int* __restrict__ deg, float* __restrict__ dinv) {
    int i = blockIdx.x * blockDim.x + threadIdx.x;
    if (i < NN) dinv[i] = rsqrtf((float)(deg[i] + 1));
}

// out[i,m] = rs[i] * sum_k X[i,k] * W[k,m]   (64x64 tile, 256 threads, 4x4/thread)
__global__ void k_gemm_rs(const float* __restrict__ X, const float* __restrict__ W,
                          const float* __restrict__ rs, float* __restrict__ out,
                          int n, int K, int M) {
    __shared__ float As[64][17];
    __shared__ float Bs[16][64];
    int bm = blockIdx.y * 64, bn = blockIdx.x * 64;
    int tid = threadIdx.x;
    int tm = (tid >> 4) << 2;   // 0..60
    int tn = (tid & 15) << 2;   // 0..60
    float acc[4][4];
#pragma unroll
    for (int i = 0; i < 4; i++)
#pragma unroll
        for (int j = 0; j < 4; j++) acc[i][j] = 0.f;

    for (int k0 = 0; k0 < K; k0 += 16) {
#pragma unroll
        for (int l = tid; l < 64 * 16; l += 256) {
            int m = l >> 4, k = l & 15;
            int gi = bm + m, gk = k0 + k;
            As[m][k] = (gi < n && gk < K) ? X[(size_t)gi * K + gk] : 0.f;
        }
#pragma unroll
        for (int l = tid; l < 16 * 64; l += 256) {
            int k = l >> 6, j = l & 63;
            int gk = k0 + k, gj = bn + j;
            Bs[k][j] = (gk < K && gj < M) ? W[(size_t)gk * M + gj] : 0.f;
        }
        __syncthreads();
#pragma unroll
        for (int k = 0; k < 16; k++) {
            float a[4], b[4];
#pragma unroll
            for (int i = 0; i < 4; i++) a[i] = As[tm + i][k];
#pragma unroll
            for (int j = 0; j < 4; j++) b[j] = Bs[k][tn + j];
#pragma unroll
            for (int i = 0; i < 4; i++)
#pragma unroll
                for (int j = 0; j < 4; j++) acc[i][j] += a[i] * b[j];
        }
        __syncthreads();
    }
#pragma unroll
    for (int i = 0; i < 4; i++) {
        int gi = bm + tm + i;
        if (gi >= n) continue;
        float sc = rs ? rs[gi] : 1.f;
#pragma unroll
        for (int j = 0; j < 4; j++) {
            int gj = bn + tn + j;
            if (gj < M) out[(size_t)gi * M + gj] = sc * acc[i][j];
        }
    }
}

// edge-list SpMM, F=32: one warp per edge
__global__ void k_spmm0(const int* __restrict__ ei, const float* __restrict__ z,
                        float* __restrict__ agg) {
    int w = (blockIdx.x * blockDim.x + threadIdx.x) >> 5;
    int lane = threadIdx.x & 31;
    if (w >= EE) return;
    int s = ei[w], d = ei[EE + w];
    atomicAdd(&agg[(size_t)d * 32 + lane], z[(size_t)s * 32 + lane]);
}

__global__ void k_combine0(const float* __restrict__ z, const float* __restrict__ agg,
                           const float* __restrict__ dinv, const float* __restrict__ b,
                           float* __restrict__ out) {
    int t = blockIdx.x * blockDim.x + threadIdx.x;
    if (t >= NN * 32) return;
    int i = t >> 5, f = t & 31;
    out[t] = eluf(dinv[i] * (agg[t] + z[t]) + b[f]);
}

__global__ void k_pnorm(const float* __restrict__ p, int F, float* __restrict__ invn) {
    __shared__ float sh[128];
    float v = (threadIdx.x < F) ? p[threadIdx.x] : 0.f;
    sh[threadIdx.x] = v * v;
    __syncthreads();
    for (int s = 64; s > 0; s >>= 1) {
        if (threadIdx.x < s) sh[threadIdx.x] += sh[threadIdx.x + s];
        __syncthreads();
    }
    if (threadIdx.x == 0) *invn = rsqrtf(sh[0]);
}

// one warp per row: s[i] = dot(x[i], p) * invnorm
__global__ void k_scores(const float* __restrict__ x, const float* __restrict__ p,
                         int n, int F, const float* __restrict__ invn,
                         float* __restrict__ s) {
    int w = (blockIdx.x * blockDim.x + threadIdx.x) >> 5;
    int lane = threadIdx.x & 31;
    if (w >= n) return;
    float acc = 0.f;
    for (int k = lane; k < F; k += 32) acc += x[(size_t)w * F + k] * p[k];
#pragma unroll
    for (int o = 16; o > 0; o >>= 1) acc += __shfl_xor_sync(0xffffffffu, acc, o);
    if (lane == 0) s[w] = acc * (*invn);
}

// rank[i] = #{j : s_j > s_i or (s_j == s_i and j < i)}  (partial over j-chunk)
__global__ void k_rank(const float* __restrict__ s, int n, int* __restrict__ rank) {
    __shared__ float st[1024];
    int i = blockIdx.x * blockDim.x + threadIdx.x;
    int j0 = blockIdx.y * 1024;
    float si = (i < n) ? s[i] : 0.f;
    for (int l = threadIdx.x; l < 1024; l += 256) st[l] = s[j0 + l];
    __syncthreads();
    int c = 0;
#pragma unroll 4
    for (int j = 0; j < 1024; j++) {
        float sj = st[j];
        c += (sj > si) || (sj == si && (j0 + j) < i);
    }
    if (i < n) atomicAdd(&rank[i], c);
}

__global__ void k_select(const int* __restrict__ rank, int n, int k,
                         int* __restrict__ idx, int* __restrict__ pos) {
    int i = blockIdx.x * blockDim.x + threadIdx.x;
    if (i >= n) return;
    int r = rank[i];
    if (pos) pos[i] = (r < k) ? r : -1;
    if (r < k) idx[r] = i;
}

// out[r,f] = elu(x[idx[r],f] * sigmoid(s[idx[r]]))
__global__ void k_gather(const float* __restrict__ x, const float* __restrict__ s,
                         const int* __restrict__ idx, int k, int F,
                         float* __restrict__ out) {
    int t = blockIdx.x * blockDim.x + threadIdx.x;
    if (t >= k * F) return;
    int r = t / F, f = t - r * F;
    int i = idx[r];
    float gate = 1.f / (1.f + expf(-s[i]));
    out[t] = eluf(x[(size_t)i * F + f] * gate);
}

// bitmap2 from original edge list (dst-keyed rows, src bits)
__global__ void k_bm_edges(const int* __restrict__ ei, const int* __restrict__ pos,
                           u32* __restrict__ bm) {
    int e = blockIdx.x * blockDim.x + threadIdx.x;
    if (e >= EE) return;
    int ps = pos[ei[e]], pd = pos[ei[EE + e]];
    if (ps >= 0 && pd >= 0)
        atomicOr(&bm[(size_t)pd * (KK1 / 32) + (ps >> 5)], 1u << (ps & 31));
}

// bm_dst[b][a] = bm_src[idx[b]][idx[a]]   (ballot -> one word store, no atomics)
__global__ void k_bm_pair(const u32* __restrict__ bm_src, int nw_src,
                          const int* __restrict__ idx, int k, u32* __restrict__ bm_dst) {
    int gw = (blockIdx.x * blockDim.x + threadIdx.x) >> 5;
    int lane = threadIdx.x & 31;
    int nw_dst = k >> 5;
    if (gw >= k * nw_dst) return;
    int b = gw / nw_dst, aw = gw - b * nw_dst;
    int a = aw * 32 + lane;
    int ia = idx[a], ib = idx[b];
    unsigned bit = (bm_src[(size_t)ib * nw_src + (ia >> 5)] >> (ia & 31)) & 1u;
    unsigned m = __ballot_sync(0xffffffffu, bit != 0);
    if (lane == 0) bm_dst[(size_t)b * nw_dst + aw] = m;
}

__global__ void k_dinv_bm(const u32* __restrict__ bm, int n, int nw,
                          float* __restrict__ dinv) {
    int i = blockIdx.x * blockDim.x + threadIdx.x;
    if (i >= n) return;
    int c = 1;
    for (int w = 0; w < nw; w++) c += __popc(bm[(size_t)i * nw + w]);
    dinv[i] = rsqrtf((float)c);
}

// bitmap SpMM: one block (F threads) per dst row; out = elu(dinv*(sum + self) + b)
__global__ void k_spmm_bm(const u32* __restrict__ bm, int nw, const float* __restrict__ z,
                          int F, const float* __restrict__ dinv,
                          const float* __restrict__ bias, float* __restrict__ out) {
    int row = blockIdx.x;
    int f = threadIdx.x;
    float acc = z[(size_t)row * F + f];   // self-loop (+I)
    const u32* r = bm + (size_t)row * nw;
    for (int w = 0; w < nw; w++) {
        u32 word = r[w];
        while (word) {
            int b = __ffs(word) - 1;
            word &= word - 1;
            int src = (w << 5) + b;
            acc += z[(size_t)src * F + f];
        }
    }
    out[(size_t)row * F + f] = eluf(dinv[row] * acc + bias[f]);
}

// xc[:, :F1] = 0 ; xc[:, F1:] = elu(skip)
__global__ void k_catfill(const float* __restrict__ skip, int n, int F1, int F2,
                          float* __restrict__ xc) {
    int F = F1 + F2;
    int t = blockIdx.x * blockDim.x + threadIdx.x;
    if (t >= n * F) return;
    int i = t / F, j = t - i * F;
    xc[t] = (j < F1) ? 0.f : eluf(skip[(size_t)i * F2 + (j - F1)]);
}

// xc[idx[r], f] = elu(xin[r, f])  for f < F1
__global__ void k_catscat(const float* __restrict__ xin, const int* __restrict__ idx,
                          int k, int F1, int Ftot, float* __restrict__ xc) {
    int t = blockIdx.x * blockDim.x + threadIdx.x;
    if (t >= k * F1) return;
    int r = t / F1, f = t - r * F1;
    xc[(size_t)idx[r] * Ftot + f] = eluf(xin[t]);
}

__global__ void k_readout(const float* __restrict__ x13, const int* __restrict__ batch,
                          float* __restrict__ gsum, u32* __restrict__ gmax,
                          float* __restrict__ cnt) {
    int t = blockIdx.x * blockDim.x + threadIdx.x;
    if (t >= NN * 32) return;
    int i = t >> 5, f = t & 31;
    int g = batch[i];
    float v = x13[t];
    atomicAdd(&gsum[g * 32 + f], v);
    atomicMax(&gmax[g * 32 + f], ford(v));
    if (f == 0) atomicAdd(&cnt[g], 1.f);
}

__global__ void k_head(const float* __restrict__ gsum, const u32* __restrict__ gmax,
                       const float* __restrict__ cnt, const float* __restrict__ Wl1,
                       const float* __restrict__ Wc, const float* __restrict__ bc,
                       float* __restrict__ out) {
    __shared__ float h[64], h2[64], lg[10], lse;
    int g = blockIdx.x, t = threadIdx.x;
    float hv = (t < 32) ? unford(gmax[g * 32 + t]) : gsum[g * 32 + (t - 32)] / cnt[g];
    h[t] = eluf(hv);
    __syncthreads();
    float acc = 0.f;
#pragma unroll
    for (int k = 0; k < 64; k++) acc += h[k] * Wl1[k * 64 + t];
    h2[t] = eluf(acc);
    __syncthreads();
    if (t < 10) {
        float a = bc[t];
#pragma unroll
        for (int k = 0; k < 64; k++) a += h2[k] * Wc[k * 10 + t];
        lg[t] = a;
    }
    __syncthreads();
    if (t == 0) {
        float m = lg[0];
        for (int c = 1; c < 10; c++) m = fmaxf(m, lg[c]);
        float se = 0.f;
        for (int c = 0; c < 10; c++) se += expf(lg[c] - m);
        lse = m + logf(se);
    }
    __syncthreads();
    if (t < 10) out[g * 10 + t] = lg[t] - lse;
}

// ------------------------------- launcher ------------------------------------
extern "C" void kernel_launch(void* const* d_in, const int* in_sizes, int n_in,
                              void* d_out, int out_size) {
    (void)in_sizes; (void)n_in; (void)out_size;
    float* B = nullptr;
    cudaGetSymbolAddress((void**)&B, g_ws);

    const float* x    = (const float*)d_in[0];
    const int*   ei   = (const int*)d_in[1];
    const int*   batch= (const int*)d_in[2];
    const float* W1 = (const float*)d_in[3],  *b1 = (const float*)d_in[4];
    const float* W2 = (const float*)d_in[5],  *b2 = (const float*)d_in[6];
    const float* W3 = (const float*)d_in[7],  *b3 = (const float*)d_in[8];
    const float* W4 = (const float*)d_in[9],  *b4 = (const float*)d_in[10];
    const float* W5 = (const float*)d_in[11], *b5 = (const float*)d_in[12];
    const float* W6 = (const float*)d_in[13], *b6 = (const float*)d_in[14];
    const float* W7 = (const float*)d_in[15], *b7 = (const float*)d_in[16];
    const float* p1 = (const float*)d_in[17];
    const float* p2 = (const float*)d_in[18];
    const float* p3 = (const float*)d_in[19];
    const float* Wl1= (const float*)d_in[20];
    const float* Wc = (const float*)d_in[21];
    const float* bc = (const float*)d_in[22];
    float* out = (float*)d_out;

    float* Z    = B + O_Z;
    float* AGG  = B + O_AGG;
    int*   DEG0 = (int*)(B + O_DEG0);
    float* DV0  = B + O_DINV0;
    float* DV2  = B + O_DINV2;
    float* DV4  = B + O_DINV4;
    float* DV6  = B + O_DINV6;
    float* SS   = B + O_S;
    int*   RANK = (int*)(B + O_RANK);
    int*   POS0 = (int*)(B + O_POS0);
    int*   I2   = (int*)(B + O_I2);
    int*   I4   = (int*)(B + O_I4);
    int*   I6   = (int*)(B + O_I6);
    u32*   BM2  = (u32*)(B + O_BM2);
    u32*   BM4  = (u32*)(B + O_BM4);
    u32*   BM6  = (u32*)(B + O_BM6);
    float* GSUM = B + O_GSUM;
    u32*   GMAX = (u32*)(B + O_GMAX);
    float* CNT  = B + O_CNT;
    float* INVN = B + O_INVN;

    // ---- zero what needs zeroing ----
    cudaMemsetAsync(DEG0, 0, NN * 4);
    cudaMemsetAsync(BM2, 0, S_BM2 * 4);
    cudaMemsetAsync(GSUM, 0, S_GSUM * 4);
    cudaMemsetAsync(GMAX, 0, S_GMAX * 4);
    cudaMemsetAsync(CNT, 0, S_CNT * 4);

    // ---- level-0 degree / dinv ----
    k_deg0<<<EE / 256, 256>>>(ei, DEG0);
    k_dinv0<<<NN / 256, 256>>>(DEG0, DV0);

    // ---- GCN1: x1 = elu(gcn(A, x, W1, b1)) ----
    k_gemm_rs<<<dim3(1, NN / 64), 256>>>(x, W1, DV0, Z, NN, 128, 32);
    cudaMemsetAsync(AGG, 0, S_AGG * 4);
    k_spmm0<<<EE * 32 / 256, 256>>>(ei, Z, AGG);
    k_combine0<<<NN * 32 / 256, 256>>>(Z, AGG, DV0, b1, B + O_X1);

    // ---- pool 1 (8192 -> 4096) ----
    k_pnorm<<<1, 128>>>(p1, 32, INVN);
    k_scores<<<NN * 32 / 256, 256>>>(B + O_X1, p1, NN, 32, INVN, SS);
    cudaMemsetAsync(RANK, 0, NN * 4);
    k_rank<<<dim3(NN / 256, NN / 1024), 256>>>(SS, NN, RANK);
    k_select<<<NN / 256, 256>>>(RANK, NN, KK1, I2, POS0);
    k_gather<<<KK1 * 32 / 256, 256>>>(B + O_X1, SS, I2, KK1, 32, B + O_X2);
    k_bm_edges<<<EE / 256, 256>>>(ei, POS0, BM2);
    k_dinv_bm<<<KK1 / 256, 256>>>(BM2, KK1, KK1 / 32, DV2);

    // ---- GCN2 ----
    k_gemm_rs<<<dim3(1, KK1 / 64), 256>>>(B + O_X2, W2, DV2, Z, KK1, 32, 64);
    k_spmm_bm<<<KK1, 64>>>(BM2, KK1 / 32, Z, 64, DV2, b2, B + O_X3);

    // ---- pool 2 (4096 -> 2048) ----
    k_pnorm<<<1, 128>>>(p2, 64, INVN);
    k_scores<<<KK1 * 32 / 256, 256>>>(B + O_X3, p2, KK1, 64, INVN, SS);
    cudaMemsetAsync(RANK, 0, KK1 * 4);
    k_rank<<<dim3(KK1 / 256, KK1 / 1024), 256>>>(SS, KK1, RANK);
    k_select<<<KK1 / 256, 256>>>(RANK, KK1, KK2, I4, (int*)nullptr);
    k_gather<<<KK2 * 64 / 256, 256>>>(B + O_X3, SS, I4, KK2, 64, B + O_X4);
    k_bm_pair<<<KK2 * (KK2 / 32) * 32 / 256, 256>>>(BM2, KK1 / 32, I4, KK2, BM4);
    k_dinv_bm<<<KK2 / 256, 256>>>(BM4, KK2, KK2 / 32, DV4);

    // ---- GCN3 ----
    k_gemm_rs<<<dim3(2, KK2 / 64), 256>>>(B + O_X4, W3, DV4, Z, KK2, 64, 128);
    k_spmm_bm<<<KK2, 128>>>(BM4, KK2 / 32, Z, 128, DV4, b3, B + O_X5);

    // ---- pool 3 (2048 -> 1024) ----
    k_pnorm<<<1, 128>>>(p3, 128, INVN);
    k_scores<<<KK2 * 32 / 256, 256>>>(B + O_X5, p3, KK2, 128, INVN, SS);
    cudaMemsetAsync(RANK, 0, KK2 * 4);
    k_rank<<<dim3(KK2 / 256, KK2 / 1024), 256>>>(SS, KK2, RANK);
    k_select<<<KK2 / 256, 256>>>(RANK, KK2, KK3, I6, (int*)nullptr);
    k_gather<<<KK3 * 128 / 256, 256>>>(B + O_X5, SS, I6, KK3, 128, B + O_X6);
    k_bm_pair<<<KK3 * (KK3 / 32) * 32 / 256, 256>>>(BM4, KK2 / 32, I6, KK3, BM6);
    k_dinv_bm<<<KK3 / 256, 256>>>(BM6, KK3, KK3 / 32, DV6);

    // ---- GCN4 ----
    k_gemm_rs<<<dim3(4, KK3 / 64), 256>>>(B + O_X6, W4, DV6, Z, KK3, 128, 256);
    k_spmm_bm<<<KK3, 256>>>(BM6, KK3 / 32, Z, 256, DV6, b4, B + O_X7);

    // ---- unpool + concat -> xc8 [2048, 384] ; GCN5 ----
    k_catfill<<<KK2 * 384 / 256, 256>>>(B + O_X5, KK2, 256, 128, B + O_XC8);
    k_catscat<<<KK3 * 256 / 256, 256>>>(B + O_X7, I6, KK3, 256, 384, B + O_XC8);
    k_gemm_rs<<<dim3(2, KK2 / 64), 256>>>(B + O_XC8, W5, DV4, Z, KK2, 384, 128);
    k_spmm_bm<<<KK2, 128>>>(BM4, KK2 / 32, Z, 128, DV4, b5, B + O_X9);

    // ---- unpool + concat -> xc10 [4096, 192] ; GCN6 ----
    k_catfill<<<KK1 * 192 / 256, 256>>>(B + O_X3, KK1, 128, 64, B + O_XC10);
    k_catscat<<<KK2 * 128 / 256, 256>>>(B + O_X9, I4, KK2, 128, 192, B + O_XC10);
    k_gemm_rs<<<dim3(1, KK1 / 64), 256>>>(B + O_XC10, W6, DV2, Z, KK1, 192, 64);
    k_spmm_bm<<<KK1, 64>>>(BM2, KK1 / 32, Z, 64, DV2, b6, B + O_X11);

    // ---- unpool + concat -> xc12 [8192, 96] ; GCN7 ----
    k_catfill<<<NN * 96 / 256, 256>>>(B + O_X1, NN, 64, 32, B + O_XC12);
    k_catscat<<<KK1 * 64 / 256, 256>>>(B + O_X11, I2, KK1, 64, 96, B + O_XC12);
    k_gemm_rs<<<dim3(1, NN / 64), 256>>>(B + O_XC12, W7, DV0, Z, NN, 96, 32);
    cudaMemsetAsync(AGG, 0, S_AGG * 4);
    k_spmm0<<<EE * 32 / 256, 256>>>(ei, Z, AGG);
    k_combine0<<<NN * 32 / 256, 256>>>(Z, AGG, DV0, b7, B + O_X13);

    // ---- readout + head ----
    k_readout<<<NN * 32 / 256, 256>>>(B + O_X13, batch, GSUM, GMAX, CNT);
    k_head<<<NG, 64>>>(GSUM, GMAX, CNT, Wl1, Wc, bc, out);
}